// round 1
// baseline (speedup 1.0000x reference)
#include <cuda_runtime.h>
#include <math.h>

#define BATCH 16384
#define HD    256
#define TILE  8      // samples per block
#define NPAIR 4      // f32x2 sample pairs
#define NCH   8      // jet channels: value, 4 tangents, 3 second-order
#define NC    (NCH*NPAIR)

typedef unsigned long long u64;

__device__ __forceinline__ u64 pack2(float a, float b) {
    u64 r; asm("mov.b64 %0, {%1, %2};" : "=l"(r) : "f"(a), "f"(b)); return r;
}
__device__ __forceinline__ void unpack2(u64 v, float& a, float& b) {
    asm("mov.b64 {%0, %1}, %2;" : "=f"(a), "=f"(b) : "l"(v));
}
// packed fp32x2 FMA: d = a*b + d  (2 fp32 lanes per instruction)
__device__ __forceinline__ void fma2(u64& d, u64 a, u64 b) {
    asm("fma.rn.f32x2 %0, %1, %2, %0;" : "+l"(d) : "l"(a), "l"(b));
}

// One hidden layer: u = s^T W (+b on value channel), tanh-jet, write back to s.
__device__ __forceinline__ void hidden_layer(float2* s2, int j,
                                             const float* __restrict__ W,
                                             const float* __restrict__ b) {
    u64 acc[NC];
#pragma unroll
    for (int c = 0; c < NC; c++) acc[c] = 0ull;

#pragma unroll 2
    for (int k0 = 0; k0 < HD; k0 += 4) {
        float w0 = __ldg(W + (k0 + 0) * HD + j);
        float w1 = __ldg(W + (k0 + 1) * HD + j);
        float w2 = __ldg(W + (k0 + 2) * HD + j);
        float w3 = __ldg(W + (k0 + 3) * HD + j);
        u64 wd0 = pack2(w0, w0), wd1 = pack2(w1, w1);
        u64 wd2 = pack2(w2, w2), wd3 = pack2(w3, w3);
#pragma unroll
        for (int c = 0; c < NC; c++) {
            const ulonglong2* p = (const ulonglong2*)(s2 + c * HD + k0);
            ulonglong2 v01 = p[0];   // pairs for k0, k0+1 (broadcast across lanes)
            ulonglong2 v23 = p[1];   // pairs for k0+2, k0+3
            fma2(acc[c], wd0, v01.x);
            fma2(acc[c], wd1, v01.y);
            fma2(acc[c], wd2, v23.x);
            fma2(acc[c], wd3, v23.y);
        }
    }
    __syncthreads();   // all reads of s done before overwrite

    float bj = b[j];
    float* base = (float*)s2;
#pragma unroll
    for (int smp = 0; smp < NPAIR; smp++) {
#pragma unroll
        for (int half = 0; half < 2; half++) {
            float u[NCH];
#pragma unroll
            for (int ch = 0; ch < NCH; ch++) {
                float a, bb; unpack2(acc[ch * NPAIR + smp], a, bb);
                u[ch] = half ? bb : a;
            }
            float h = tanhf(u[0] + bj);
            float d = 1.f - h * h;
            base[((0 * NPAIR + smp) * HD + j) * 2 + half] = h;
#pragma unroll
            for (int i = 0; i < 4; i++)
                base[(((1 + i) * NPAIR + smp) * HD + j) * 2 + half] = d * u[1 + i];
#pragma unroll
            for (int i = 0; i < 3; i++)
                base[(((5 + i) * NPAIR + smp) * HD + j) * 2 + half] =
                    d * (u[5 + i] - 2.f * h * u[1 + i] * u[1 + i]);
        }
    }
    __syncthreads();
}

__global__ __launch_bounds__(256, 2)
void grad_kernel(const float* __restrict__ x,
                 const float* __restrict__ W0, const float* __restrict__ b0,
                 const float* __restrict__ W1, const float* __restrict__ b1,
                 const float* __restrict__ W2, const float* __restrict__ b2,
                 const float* __restrict__ W3, const float* __restrict__ b3,
                 const float* __restrict__ Wo, const float* __restrict__ bo,
                 float* __restrict__ out) {
    extern __shared__ __align__(16) float2 s2[];    // NC*HD float2 (64 KB)
    float* outbuf = (float*)(s2 + NC * HD);         // TILE*16 floats
    const int j  = threadIdx.x;
    const int s0 = blockIdx.x * TILE;

    // ---- layer 0: 4 -> 256 (input tangents are e_i; second-order in = 0)
    {
        float w0v[4];
#pragma unroll
        for (int i = 0; i < 4; i++) w0v[i] = W0[i * HD + j];
        float b0j = b0[j];
        float* base = (float*)s2;
#pragma unroll
        for (int sm = 0; sm < TILE; sm++) {
            const float4 xv = *(const float4*)(x + (size_t)(s0 + sm) * 4);
            float uu = b0j + xv.x * w0v[0] + xv.y * w0v[1] + xv.z * w0v[2] + xv.w * w0v[3];
            float h = tanhf(uu);
            float d = 1.f - h * h;
            int smp = sm >> 1, half = sm & 1;
            base[((0 * NPAIR + smp) * HD + j) * 2 + half] = h;
#pragma unroll
            for (int i = 0; i < 4; i++)
                base[(((1 + i) * NPAIR + smp) * HD + j) * 2 + half] = d * w0v[i];
#pragma unroll
            for (int i = 0; i < 3; i++)
                base[(((5 + i) * NPAIR + smp) * HD + j) * 2 + half] =
                    -2.f * h * d * w0v[i] * w0v[i];
        }
    }
    __syncthreads();

    // ---- hidden layers 1..3: 256 -> 256
    hidden_layer(s2, j, W1, b1);
    hidden_layer(s2, j, W2, b2);
    hidden_layer(s2, j, W3, b3);

    // ---- output head: 256 -> 2 for all 8 channels x 8 samples (128 dots)
    if (j < 128) {
        int m  = j & 1;
        int ch = (j >> 1) & 7;
        int sm = j >> 4;
        int smp = sm >> 1, half = sm & 1;
        const float* base = (const float*)s2;
        float o = 0.f;
#pragma unroll 4
        for (int k = 0; k < HD; k++)
            o += __ldg(Wo + k * 2 + m) * base[((ch * NPAIR + smp) * HD + k) * 2 + half];
        if (ch == 0) o += bo[m];
        outbuf[j] = o;
    }
    __syncthreads();

    // ---- final per-sample combine + global stores
    if (j < TILE) {
        int sm = j;
        const float* ob = outbuf + sm * 16;   // [ch][m]
        float c  = ob[0 * 2 + 0];
        float Fi = ob[0 * 2 + 1];
        float cj[4], Fj[4];
#pragma unroll
        for (int i = 0; i < 4; i++) { cj[i] = ob[(1 + i) * 2 + 0]; Fj[i] = ob[(1 + i) * 2 + 1]; }
        float trHc = 0.f, FiLap = 0.f;
#pragma unroll
        for (int i = 0; i < 3; i++) { trHc += ob[(5 + i) * 2 + 0]; FiLap += ob[(5 + i) * 2 + 1]; }
        float dotg = cj[0] * Fj[0] + cj[1] * Fj[1] + cj[2] * Fj[2];
        float sumg = cj[0] + cj[1] + cj[2];
        // j_div = -D*tr(Hc) - K*(c_grd.Fi_grd + c*Fi_lap) + V*sum(c_grd);  D=K=1, V=0.1
        float jdiv = -trHc - (dotg + c * FiLap) + 0.1f * sumg;

        int idx = s0 + sm;
        out[idx]                      = c;        // c            [0, B)
        out[BATCH + idx]              = cj[3];    // c_t          [B, 2B)
        out[2 * BATCH + idx * 3 + 0]  = cj[0];    // c_grd        [2B, 5B)
        out[2 * BATCH + idx * 3 + 1]  = cj[1];
        out[2 * BATCH + idx * 3 + 2]  = cj[2];
        out[5 * BATCH + idx]          = Fi;       // Fi           [5B, 6B)
        out[6 * BATCH + idx * 3 + 0]  = Fj[0];    // Fi_grd       [6B, 9B)
        out[6 * BATCH + idx * 3 + 1]  = Fj[1];
        out[6 * BATCH + idx * 3 + 2]  = Fj[2];
        out[9 * BATCH + idx]          = FiLap;    // Fi_lap       [9B, 10B)
        out[10 * BATCH + idx]         = jdiv;     // j_div        [10B, 11B)
    }
}

extern "C" void kernel_launch(void* const* d_in, const int* in_sizes, int n_in,
                              void* d_out, int out_size) {
    const float* x  = (const float*)d_in[0];
    const float* W0 = (const float*)d_in[1];
    const float* b0 = (const float*)d_in[2];
    const float* W1 = (const float*)d_in[3];
    const float* b1 = (const float*)d_in[4];
    const float* W2 = (const float*)d_in[5];
    const float* b2 = (const float*)d_in[6];
    const float* W3 = (const float*)d_in[7];
    const float* b3 = (const float*)d_in[8];
    const float* Wo = (const float*)d_in[9];
    const float* bo = (const float*)d_in[10];

    size_t smem = (size_t)NC * HD * sizeof(float2) + TILE * 16 * sizeof(float);
    cudaFuncSetAttribute(grad_kernel, cudaFuncAttributeMaxDynamicSharedMemorySize, (int)smem);
    grad_kernel<<<BATCH / TILE, 256, smem>>>(x, W0, b0, W1, b1, W2, b2, W3, b3,
                                             Wo, bo, (float*)d_out);
}

// round 2
// speedup vs baseline: 1.4386x; 1.4386x over previous
#include <cuda_runtime.h>
#include <math.h>

#define BATCH 16384
#define HD    256
#define TILE  8            // samples per block
#define KC    32           // k-chunk for weight staging
#define NCHUNK (HD / KC)   // 8

typedef unsigned long long u64;
typedef unsigned int u32;

__device__ __forceinline__ u64 pack2(float a, float b) {
    u64 r; asm("mov.b64 %0, {%1, %2};" : "=l"(r) : "f"(a), "f"(b)); return r;
}
__device__ __forceinline__ void unpack2(u64 v, float& a, float& b) {
    asm("mov.b64 {%0, %1}, %2;" : "=f"(a), "=f"(b) : "l"(v));
}
__device__ __forceinline__ void fma2(u64& d, u64 a, u64 b) {
    asm("fma.rn.f32x2 %0, %1, %2, %0;" : "+l"(d) : "l"(a), "l"(b));
}
__device__ __forceinline__ u32 s2u(const void* p) {
    return (u32)__cvta_generic_to_shared(p);
}
__device__ __forceinline__ void cpasync16(u32 dst, const void* src) {
    asm volatile("cp.async.cg.shared.global [%0], [%1], 16;" :: "r"(dst), "l"(src));
}
#define CP_COMMIT asm volatile("cp.async.commit_group;")

// S layout: row k = 256 bytes (64 floats, m = sample*8 + channel), XOR swizzle
// on bits 5-7 of the within-row byte offset keyed by (k>>1)&7.
__device__ __forceinline__ int swz(int k) { return ((k >> 1) & 7) << 5; }

// tanh-jet: u[0]=value(+bias), u[1..4]=1st-order dirs, u[5..7]=2nd-order dirs 0..2
__device__ __forceinline__ void write_jet(char* S, int jcol, int ts,
                                          const float u[8], float bj) {
    float h = tanhf(u[0] + bj);
    float d = 1.f - h * h;
    float4 v0, v1;
    v0.x = h;
    v0.y = d * u[1];
    v0.z = d * u[2];
    v0.w = d * u[3];
    v1.x = d * u[4];
    v1.y = d * (u[5] - 2.f * h * u[1] * u[1]);
    v1.z = d * (u[6] - 2.f * h * u[2] * u[2]);
    v1.w = d * (u[7] - 2.f * h * u[3] * u[3]);
    int base = (ts * 32) ^ swz(jcol);
    *(float4*)(S + jcol * 256 + base)      = v0;
    *(float4*)(S + jcol * 256 + base + 16) = v1;
}

__device__ __forceinline__ void load_chunk(float* dst, const float* __restrict__ W,
                                           int c, int tid) {
    const float4* g = (const float4*)(W + c * KC * HD);
    u32 d = s2u(dst);
#pragma unroll
    for (int q = 0; q < 8; q++)
        cpasync16(d + (u32)(q * 256 + tid) * 16u, g + q * 256 + tid);
}

__device__ void hidden_layer(char* S, float* Ws, int tid, int ts, int tj,
                             const float* __restrict__ W,
                             const float* __restrict__ b) {
    u64 acc[32];
#pragma unroll
    for (int c = 0; c < 32; c++) acc[c] = 0ull;

    load_chunk(Ws, W, 0, tid);
    CP_COMMIT;

    for (int c = 0; c < NCHUNK; c++) {
        if (c + 1 < NCHUNK) {
            load_chunk(Ws + ((c + 1) & 1) * KC * HD, W, c + 1, tid);
            CP_COMMIT;
            asm volatile("cp.async.wait_group 1;");
        } else {
            asm volatile("cp.async.wait_group 0;");
        }
        __syncthreads();

        const float* Wk = Ws + (c & 1) * KC * HD;
#pragma unroll 2
        for (int kk = 0; kk < KC; kk++) {
            int k = c * KC + kk;
            int base = (ts * 32) ^ swz(k);
            const char* rowp = S + k * 256;
            float4 a0 = *(const float4*)(rowp + base);
            float4 a1 = *(const float4*)(rowp + base + 16);
            u64 w0 = *(const u64*)(Wk + kk * HD + 0 * 64 + 2 * tj);
            u64 w1 = *(const u64*)(Wk + kk * HD + 1 * 64 + 2 * tj);
            u64 w2 = *(const u64*)(Wk + kk * HD + 2 * 64 + 2 * tj);
            u64 w3 = *(const u64*)(Wk + kk * HD + 3 * 64 + 2 * tj);
            u64 sp[8];
            sp[0] = pack2(a0.x, a0.x); sp[1] = pack2(a0.y, a0.y);
            sp[2] = pack2(a0.z, a0.z); sp[3] = pack2(a0.w, a0.w);
            sp[4] = pack2(a1.x, a1.x); sp[5] = pack2(a1.y, a1.y);
            sp[6] = pack2(a1.z, a1.z); sp[7] = pack2(a1.w, a1.w);
#pragma unroll
            for (int ch = 0; ch < 8; ch++) {
                fma2(acc[ch * 4 + 0], sp[ch], w0);
                fma2(acc[ch * 4 + 1], sp[ch], w1);
                fma2(acc[ch * 4 + 2], sp[ch], w2);
                fma2(acc[ch * 4 + 3], sp[ch], w3);
            }
        }
        __syncthreads();   // all reads of this Ws buffer done before re-fill
    }

    // epilogue: all threads are past the last sync -> S fully consumed; overwrite.
#pragma unroll
    for (int g = 0; g < 4; g++) {
        int jb = 64 * g + 2 * tj;
        float2 bp = *(const float2*)(b + jb);
        float ulo[8], uhi[8];
#pragma unroll
        for (int ch = 0; ch < 8; ch++) unpack2(acc[ch * 4 + g], ulo[ch], uhi[ch]);
        write_jet(S, jb,     ts, ulo, bp.x);
        write_jet(S, jb + 1, ts, uhi, bp.y);
    }
    __syncthreads();
}

__global__ __launch_bounds__(256)
void grad_kernel(const float* __restrict__ x,
                 const float* __restrict__ W0, const float* __restrict__ b0,
                 const float* __restrict__ W1, const float* __restrict__ b1,
                 const float* __restrict__ W2, const float* __restrict__ b2,
                 const float* __restrict__ W3, const float* __restrict__ b3,
                 const float* __restrict__ Wo, const float* __restrict__ bo,
                 float* __restrict__ out) {
    extern __shared__ __align__(16) char smem[];
    char*  S      = smem;                       // 64 KB: S[k][64 floats], swizzled
    float* Ws     = (float*)(smem + 65536);     // 64 KB: 2 x (KC x 256) weight chunks
    float* outbuf = (float*)(smem + 131072);    // 128 floats

    const int tid = threadIdx.x;
    const int ts  = tid >> 5;   // sample within tile (warp id)
    const int tj  = tid & 31;   // column block
    const int s0  = blockIdx.x * TILE;

    // ---- layer 0: 4 -> 256, jet seeded with identity tangents
    {
        const float4 xv = *(const float4*)(x + (size_t)(s0 + ts) * 4);
#pragma unroll
        for (int g = 0; g < 4; g++) {
            int jb = 64 * g + 2 * tj;
            float2 w0p[4];
#pragma unroll
            for (int i = 0; i < 4; i++) w0p[i] = *(const float2*)(W0 + i * HD + jb);
            float2 b0p = *(const float2*)(b0 + jb);
#pragma unroll
            for (int p = 0; p < 2; p++) {
                float wv[4];
#pragma unroll
                for (int i = 0; i < 4; i++) wv[i] = p ? w0p[i].y : w0p[i].x;
                float u[8];
                u[0] = xv.x * wv[0] + xv.y * wv[1] + xv.z * wv[2] + xv.w * wv[3];
                u[1] = wv[0]; u[2] = wv[1]; u[3] = wv[2]; u[4] = wv[3];
                u[5] = 0.f; u[6] = 0.f; u[7] = 0.f;
                write_jet(S, jb + p, ts, u, p ? b0p.y : b0p.x);
            }
        }
    }
    __syncthreads();

    hidden_layer(S, Ws, tid, ts, tj, W1, b1);
    hidden_layer(S, Ws, tid, ts, tj, W2, b2);
    hidden_layer(S, Ws, tid, ts, tj, W3, b3);

    // ---- output head: 64 rows x 2 outputs = 128 dot products of length 256
    if (tid < 128) {
        int dout = tid & 1;
        int m    = tid >> 1;          // m = sample*8 + channel
        float o = 0.f;
#pragma unroll 4
        for (int k = 0; k < HD; k++) {
            float sv = *(const float*)(S + k * 256 + ((m * 4) ^ swz(k)));
            o += sv * __ldg(Wo + k * 2 + dout);
        }
        if ((m & 7) == 0) o += bo[dout];
        outbuf[(m >> 3) * 16 + (m & 7) * 2 + dout] = o;
    }
    __syncthreads();

    // ---- per-sample combine + stores
    if (tid < TILE) {
        int sm = tid;
        const float* ob = outbuf + sm * 16;   // [ch][dout]
        float c  = ob[0];
        float Fi = ob[1];
        float cj[4], Fj[4];
#pragma unroll
        for (int i = 0; i < 4; i++) { cj[i] = ob[(1 + i) * 2]; Fj[i] = ob[(1 + i) * 2 + 1]; }
        float trHc = 0.f, FiLap = 0.f;
#pragma unroll
        for (int i = 0; i < 3; i++) { trHc += ob[(5 + i) * 2]; FiLap += ob[(5 + i) * 2 + 1]; }
        float dotg = cj[0] * Fj[0] + cj[1] * Fj[1] + cj[2] * Fj[2];
        float sumg = cj[0] + cj[1] + cj[2];
        float jdiv = -trHc - (dotg + c * FiLap) + 0.1f * sumg;

        int idx = s0 + sm;
        out[idx]                     = c;
        out[BATCH + idx]             = cj[3];
        out[2 * BATCH + idx * 3 + 0] = cj[0];
        out[2 * BATCH + idx * 3 + 1] = cj[1];
        out[2 * BATCH + idx * 3 + 2] = cj[2];
        out[5 * BATCH + idx]         = Fi;
        out[6 * BATCH + idx * 3 + 0] = Fj[0];
        out[6 * BATCH + idx * 3 + 1] = Fj[1];
        out[6 * BATCH + idx * 3 + 2] = Fj[2];
        out[9 * BATCH + idx]         = FiLap;
        out[10 * BATCH + idx]        = jdiv;
    }
}

extern "C" void kernel_launch(void* const* d_in, const int* in_sizes, int n_in,
                              void* d_out, int out_size) {
    const float* x  = (const float*)d_in[0];
    const float* W0 = (const float*)d_in[1];
    const float* b0 = (const float*)d_in[2];
    const float* W1 = (const float*)d_in[3];
    const float* b1 = (const float*)d_in[4];
    const float* W2 = (const float*)d_in[5];
    const float* b2 = (const float*)d_in[6];
    const float* W3 = (const float*)d_in[7];
    const float* b3 = (const float*)d_in[8];
    const float* Wo = (const float*)d_in[9];
    const float* bo = (const float*)d_in[10];

    size_t smem = 131072 + 128 * sizeof(float);
    cudaFuncSetAttribute(grad_kernel, cudaFuncAttributeMaxDynamicSharedMemorySize, (int)smem);
    grad_kernel<<<BATCH / TILE, 256, smem>>>(x, W0, b0, W1, b1, W2, b2, W3, b3,
                                             Wo, bo, (float*)d_out);
}

// round 5
// speedup vs baseline: 2.6435x; 1.8376x over previous
#include <cuda_runtime.h>
#include <cuda_fp16.h>
#include <math.h>

#define BATCH   16384
#define HD      256
#define SAMPLES 16
#define MROWS   128
#define NLAYER  3
#define TOTCH   24          // 3 layers x 8 chunks of K=32

typedef unsigned int u32;

// ---------------- global scratch: W^T split into fp16 hi/lo planes
__device__ __align__(16) __half g_Whi[NLAYER * HD * HD];
__device__ __align__(16) __half g_Wlo[NLAYER * HD * HD];

__global__ void prep_split(const float* __restrict__ W1,
                           const float* __restrict__ W2,
                           const float* __restrict__ W3) {
    int b = blockIdx.x;               // 0..767
    int layer = b >> 8, n = b & 255, k = threadIdx.x;
    const float* W = layer == 0 ? W1 : (layer == 1 ? W2 : W3);
    float v = W[k * HD + n];
    __half hi = __float2half_rn(v);
    __half lo = __float2half_rn(v - __half2float(hi));
    g_Whi[(layer * HD + n) * HD + k] = hi;
    g_Wlo[(layer * HD + n) * HD + k] = lo;
}

// ---------------- smem layout (bytes)
#define SROW    528          // 256 halfs + 16B pad (33 chunks, coprime 8)
#define WROW    80           // 32 halfs + 16B pad  (5 chunks, coprime 8)
#define SM_SHI  0            // 128*528 = 67584
#define SM_SLO  67584        // 67584            -> 135168
#define SM_WB   135168       // 2 bufs x 2 planes x 256*80 = 81920 -> 217088
#define WB_BUF  40960
#define WB_LO   20480
#define SM_BIAS 217088       // 3*1024 -> 220160
#define SM_WO   220160       // 2048   -> 222208
#define SM_OUT  222208       // 1024   -> 223232
#define SM_TOT  223232

__device__ __forceinline__ u32 s2u(const void* p) { return (u32)__cvta_generic_to_shared(p); }

__device__ __forceinline__ void cpasync16(u32 dst, const void* src) {
    asm volatile("cp.async.cg.shared.global [%0], [%1], 16;" :: "r"(dst), "l"(src));
}
__device__ __forceinline__ void ldsm4(u32* d, u32 addr) {
    asm volatile("ldmatrix.sync.aligned.m8n8.x4.shared.b16 {%0,%1,%2,%3}, [%4];"
                 : "=r"(d[0]), "=r"(d[1]), "=r"(d[2]), "=r"(d[3]) : "r"(addr));
}
__device__ __forceinline__ void mma16816(float* c, const u32* a, u32 b0, u32 b1) {
    asm volatile("mma.sync.aligned.m16n8k16.row.col.f32.f16.f16.f32 "
                 "{%0,%1,%2,%3},{%4,%5,%6,%7},{%8,%9},{%0,%1,%2,%3};"
                 : "+f"(c[0]), "+f"(c[1]), "+f"(c[2]), "+f"(c[3])
                 : "r"(a[0]), "r"(a[1]), "r"(a[2]), "r"(a[3]), "r"(b0), "r"(b1));
}
__device__ __forceinline__ float ftanh(float u) {
    float a = fabsf(u);
    float t = __expf(-2.f * a);
    float h = __fdividef(1.f - t, 1.f + t);
    return copysignf(h, u);
}
// split store: hi + lo planes at (row, k) (k even, 2 values)
__device__ __forceinline__ void store_split(char* smem, int row, int k,
                                            float vx, float vy) {
    __half hx = __float2half_rn(vx), hy = __float2half_rn(vy);
    float lx = vx - __half2float(hx), ly = vy - __half2float(hy);
    __half2 hp = __halves2half2(hx, hy);
    __half2 lp = __halves2half2(__float2half_rn(lx), __float2half_rn(ly));
    *(u32*)(smem + SM_SHI + row * SROW + k * 2) = *(u32*)&hp;
    *(u32*)(smem + SM_SLO + row * SROW + k * 2) = *(u32*)&lp;
}

// one K=32 chunk of W^T (both planes): 256 rows x 4 x 16B per plane = 1024
// transfers/plane; 512 threads x 2 iters, both planes per iter.
__device__ __forceinline__ void load_chunk(char* smem, int cg, int tid) {
    const int layer = cg >> 3, c = cg & 7, bsel = cg & 1;
    const __half* sh = g_Whi + layer * (HD * HD) + c * 32;
    const __half* sl = g_Wlo + layer * (HD * HD) + c * 32;
    const u32 dH = s2u(smem + SM_WB) + (u32)(bsel * WB_BUF);
    const u32 dL = dH + WB_LO;
#pragma unroll
    for (int t = 0; t < 2; t++) {
        int i = tid + t * 512;            // 0..1023
        int n = i >> 2, s = i & 3;        // n: 0..255, s: 0..3
        u32 off = (u32)(n * WROW + s * 16);
        cpasync16(dH + off, sh + n * HD + s * 8);
        cpasync16(dL + off, sl + n * HD + s * 8);
    }
    asm volatile("cp.async.commit_group;");
}

__global__ __launch_bounds__(512, 1)
void grad_kernel(const float* __restrict__ x,
                 const float* __restrict__ W0, const float* __restrict__ b0,
                 const float* __restrict__ b1, const float* __restrict__ b2,
                 const float* __restrict__ b3,
                 const float* __restrict__ Wo, const float* __restrict__ bo,
                 float* __restrict__ out) {
    extern __shared__ __align__(16) char smem[];
    const int tid  = threadIdx.x;
    const int wid  = tid >> 5;
    const int lane = tid & 31;
    const int wm = wid & 7, wn = wid >> 3;
    const int m0 = wm * 16, nb0 = wn * 128;
    const int s0 = blockIdx.x * SAMPLES;

    // ---- stage bias + Wo
    for (int i = tid; i < HD; i += 512) {
        ((float*)(smem + SM_BIAS))[i]        = b1[i];
        ((float*)(smem + SM_BIAS + 1024))[i] = b2[i];
        ((float*)(smem + SM_BIAS + 2048))[i] = b3[i];
    }
    ((float*)(smem + SM_WO))[tid] = Wo[tid];

    load_chunk(smem, 0, tid);   // prefetch overlaps layer0

    // ---- layer 0: 4 -> 256 jet, write split planes
    {
        const int samp = tid >> 5, kg = tid & 31;
        const float4 xv = __ldg((const float4*)x + (s0 + samp));
#pragma unroll
        for (int jp = 0; jp < 4; jp++) {
            const int k = kg * 8 + jp * 2;
            float vv[2][8];
#pragma unroll
            for (int e = 0; e < 2; e++) {
                const int ke = k + e;
                float w0 = __ldg(W0 + 0 * HD + ke), w1 = __ldg(W0 + 1 * HD + ke);
                float w2 = __ldg(W0 + 2 * HD + ke), w3 = __ldg(W0 + 3 * HD + ke);
                float u0 = __ldg(b0 + ke) + xv.x * w0 + xv.y * w1 + xv.z * w2 + xv.w * w3;
                float h = ftanh(u0), d = 1.f - h * h;
                vv[e][0] = h;
                vv[e][1] = d * w0; vv[e][2] = d * w1; vv[e][3] = d * w2; vv[e][4] = d * w3;
                float c2 = -2.f * h * d;
                vv[e][5] = c2 * w0 * w0; vv[e][6] = c2 * w1 * w1; vv[e][7] = c2 * w2 * w2;
            }
#pragma unroll
            for (int ch = 0; ch < 8; ch++)
                store_split(smem, samp * 8 + ch, k, vv[0][ch], vv[1][ch]);
        }
    }
    __syncthreads();

    // ---- lane bases for ldmatrix
    const int lt = lane >> 3, lr = lane & 7;
    const u32 aBase = (u32)((m0 + ((lt & 1) << 3) + lr) * SROW + ((lt >> 1) << 4));
    const u32 aHi = s2u(smem + SM_SHI) + aBase;
    const u32 aLo = s2u(smem + SM_SLO) + aBase;
    const u32 bOff = (u32)((nb0 + ((lt >> 1) << 3) + lr) * WROW + ((lt & 1) << 4));
    const int q = lane & 3, ch = lane >> 2;
    const int srcl = (ch >= 5) ? (((ch - 4) << 2) + q) : lane;

    float acc[16][4];

    for (int L = 0; L < NLAYER; L++) {
#pragma unroll
        for (int nt = 0; nt < 16; nt++)
#pragma unroll
            for (int j = 0; j < 4; j++) acc[nt][j] = 0.f;

        for (int c = 0; c < 8; c++) {
            const int cg = L * 8 + c;
            if (cg + 1 < TOTCH) {
                load_chunk(smem, cg + 1, tid);
                asm volatile("cp.async.wait_group 1;");
            } else {
                asm volatile("cp.async.wait_group 0;");
            }
            __syncthreads();

            const u32 wb = s2u(smem + SM_WB) + (u32)((cg & 1) * WB_BUF) + bOff;
#pragma unroll
            for (int kt = 0; kt < 2; kt++) {
                const u32 ka = (u32)(c * 64 + kt * 32);
                u32 Ah[4], Al[4];
                ldsm4(Ah, aHi + ka);
                ldsm4(Al, aLo + ka);
                const u32 wk = wb + (u32)(kt * 32);
#pragma unroll
                for (int np = 0; np < 8; np++) {
                    u32 Bh[4], Bl[4];
                    ldsm4(Bh, wk + (u32)(np * 16 * WROW));
                    ldsm4(Bl, wk + (u32)(np * 16 * WROW) + WB_LO);
                    mma16816(acc[2 * np],     Ah, Bh[0], Bh[1]);
                    mma16816(acc[2 * np],     Ah, Bl[0], Bl[1]);
                    mma16816(acc[2 * np],     Al, Bh[0], Bh[1]);
                    mma16816(acc[2 * np + 1], Ah, Bh[2], Bh[3]);
                    mma16816(acc[2 * np + 1], Ah, Bl[2], Bl[3]);
                    mma16816(acc[2 * np + 1], Al, Bh[2], Bh[3]);
                }
            }
            __syncthreads();   // buffer consumed before next-next load
        }

        // ---- epilogue: tanh-jet in registers, write split planes
        const float* bs = (const float*)(smem + SM_BIAS) + L * HD;
#pragma unroll
        for (int nt = 0; nt < 16; nt++) {
            const int n = nb0 + nt * 8 + 2 * q;
            const float2 bn = *(const float2*)(bs + n);
#pragma unroll
            for (int sh = 0; sh < 2; sh++) {
                float ux = acc[nt][sh * 2 + 0], uy = acc[nt][sh * 2 + 1];
                float u0x = __shfl_sync(0xffffffffu, ux, q);
                float u0y = __shfl_sync(0xffffffffu, uy, q);
                float u1x = __shfl_sync(0xffffffffu, ux, srcl);
                float u1y = __shfl_sync(0xffffffffu, uy, srcl);
                float hx = ftanh(u0x + bn.x), hy = ftanh(u0y + bn.y);
                float dx = 1.f - hx * hx, dy = 1.f - hy * hy;
                float vx, vy;
                if (ch == 0)      { vx = hx; vy = hy; }
                else if (ch < 5)  { vx = dx * ux; vy = dy * uy; }
                else {
                    vx = dx * (ux - 2.f * hx * u1x * u1x);
                    vy = dy * (uy - 2.f * hy * u1y * u1y);
                }
                store_split(smem, m0 + sh * 8 + ch, n, vx, vy);
            }
        }
        __syncthreads();
    }

    // ---- output head: 128 rows x 2 outs; 4 threads per row (64 k each)
    {
        const int m = tid >> 2, kq = tid & 3;
        const char* ph = smem + SM_SHI + m * SROW;
        const char* pl = smem + SM_SLO + m * SROW;
        const float* wos = (const float*)(smem + SM_WO);
        float o0 = 0.f, o1 = 0.f;
#pragma unroll 4
        for (int kk = 0; kk < 32; kk++) {
            const int k = kq * 64 + ((kk + kq * 8) & 31) * 2;   // rotate: no bank clash
            u32 hp = *(const u32*)(ph + k * 2);
            u32 lp = *(const u32*)(pl + k * 2);
            float2 vh = __half22float2(*(__half2*)&hp);
            float2 vl = __half22float2(*(__half2*)&lp);
            float v0 = vh.x + vl.x, v1 = vh.y + vl.y;
            float2 w0 = *(const float2*)(wos + k * 2);
            float2 w1 = *(const float2*)(wos + k * 2 + 2);
            o0 += v0 * w0.x + v1 * w1.x;
            o1 += v0 * w0.y + v1 * w1.y;
        }
        o0 += __shfl_xor_sync(0xffffffffu, o0, 1);
        o0 += __shfl_xor_sync(0xffffffffu, o0, 2);
        o1 += __shfl_xor_sync(0xffffffffu, o1, 1);
        o1 += __shfl_xor_sync(0xffffffffu, o1, 2);
        if (kq == 0) {
            if ((m & 7) == 0) { o0 += __ldg(bo); o1 += __ldg(bo + 1); }
            ((float*)(smem + SM_OUT))[m * 2 + 0] = o0;
            ((float*)(smem + SM_OUT))[m * 2 + 1] = o1;
        }
    }
    __syncthreads();

    // ---- per-sample combine + stores
    if (tid < SAMPLES) {
        const float* ob = (const float*)(smem + SM_OUT) + tid * 16;  // [ch][dout]
        float c  = ob[0], Fi = ob[1];
        float cj[4], Fj[4];
#pragma unroll
        for (int i = 0; i < 4; i++) { cj[i] = ob[(1 + i) * 2]; Fj[i] = ob[(1 + i) * 2 + 1]; }
        float trHc = 0.f, FiLap = 0.f;
#pragma unroll
        for (int i = 0; i < 3; i++) { trHc += ob[(5 + i) * 2]; FiLap += ob[(5 + i) * 2 + 1]; }
        float dotg = cj[0] * Fj[0] + cj[1] * Fj[1] + cj[2] * Fj[2];
        float sumg = cj[0] + cj[1] + cj[2];
        float jdiv = -trHc - (dotg + c * FiLap) + 0.1f * sumg;

        const int idx = s0 + tid;
        out[idx]                     = c;
        out[BATCH + idx]             = cj[3];
        out[2 * BATCH + idx * 3 + 0] = cj[0];
        out[2 * BATCH + idx * 3 + 1] = cj[1];
        out[2 * BATCH + idx * 3 + 2] = cj[2];
        out[5 * BATCH + idx]         = Fi;
        out[6 * BATCH + idx * 3 + 0] = Fj[0];
        out[6 * BATCH + idx * 3 + 1] = Fj[1];
        out[6 * BATCH + idx * 3 + 2] = Fj[2];
        out[9 * BATCH + idx]         = FiLap;
        out[10 * BATCH + idx]        = jdiv;
    }
}

extern "C" void kernel_launch(void* const* d_in, const int* in_sizes, int n_in,
                              void* d_out, int out_size) {
    const float* x  = (const float*)d_in[0];
    const float* W0 = (const float*)d_in[1];
    const float* b0 = (const float*)d_in[2];
    const float* W1 = (const float*)d_in[3];
    const float* b1 = (const float*)d_in[4];
    const float* W2 = (const float*)d_in[5];
    const float* b2 = (const float*)d_in[6];
    const float* W3 = (const float*)d_in[7];
    const float* b3 = (const float*)d_in[8];
    const float* Wo = (const float*)d_in[9];
    const float* bo = (const float*)d_in[10];

    prep_split<<<NLAYER * HD, HD>>>(W1, W2, W3);

    cudaFuncSetAttribute(grad_kernel, cudaFuncAttributeMaxDynamicSharedMemorySize, SM_TOT);
    grad_kernel<<<BATCH / SAMPLES, 512, SM_TOT>>>(x, W0, b0, b1, b2, b3,
                                                  Wo, bo, (float*)d_out);
}

// round 6
// speedup vs baseline: 2.9681x; 1.1228x over previous
#include <cuda_runtime.h>
#include <cuda_fp16.h>
#include <math.h>

#define BATCH   16384
#define HD      256
#define SAMPLES 16
#define MROWS   128
#define NLAYER  3
#define TOTCH   24          // 3 layers x 8 chunks of K=32
#define NTHREADS 1024

typedef unsigned int u32;

// ---------------- global scratch: W^T split into fp16 hi/lo planes
__device__ __align__(16) __half g_Whi[NLAYER * HD * HD];
__device__ __align__(16) __half g_Wlo[NLAYER * HD * HD];

__global__ void prep_split(const float* __restrict__ W1,
                           const float* __restrict__ W2,
                           const float* __restrict__ W3) {
    int b = blockIdx.x;               // 0..767
    int layer = b >> 8, n = b & 255, k = threadIdx.x;
    const float* W = layer == 0 ? W1 : (layer == 1 ? W2 : W3);
    float v = W[k * HD + n];
    __half hi = __float2half_rn(v);
    __half lo = __float2half_rn(v - __half2float(hi));
    g_Whi[(layer * HD + n) * HD + k] = hi;
    g_Wlo[(layer * HD + n) * HD + k] = lo;
}

// ---------------- smem layout (bytes)
#define SROW    528          // 256 halfs + 16B pad (33 chunks, coprime 8)
#define WROW    80           // 32 halfs + 16B pad  (5 chunks, coprime 8)
#define SM_SHI  0            // 128*528 = 67584
#define SM_SLO  67584        // 67584            -> 135168
#define SM_WB   135168       // 2 bufs x 2 planes x 256*80 = 81920 -> 217088
#define WB_BUF  40960
#define WB_LO   20480
#define SM_BIAS 217088       // 3*1024 -> 220160
#define SM_WO   220160       // 2048   -> 222208
#define SM_OUT  222208       // 1024   -> 223232
#define SM_TOT  223232

__device__ __forceinline__ u32 s2u(const void* p) { return (u32)__cvta_generic_to_shared(p); }

__device__ __forceinline__ void cpasync16(u32 dst, const void* src) {
    asm volatile("cp.async.cg.shared.global [%0], [%1], 16;" :: "r"(dst), "l"(src));
}
__device__ __forceinline__ void ldsm4(u32* d, u32 addr) {
    asm volatile("ldmatrix.sync.aligned.m8n8.x4.shared.b16 {%0,%1,%2,%3}, [%4];"
                 : "=r"(d[0]), "=r"(d[1]), "=r"(d[2]), "=r"(d[3]) : "r"(addr));
}
__device__ __forceinline__ void mma16816(float* c, const u32* a, u32 b0, u32 b1) {
    asm volatile("mma.sync.aligned.m16n8k16.row.col.f32.f16.f16.f32 "
                 "{%0,%1,%2,%3},{%4,%5,%6,%7},{%8,%9},{%0,%1,%2,%3};"
                 : "+f"(c[0]), "+f"(c[1]), "+f"(c[2]), "+f"(c[3])
                 : "r"(a[0]), "r"(a[1]), "r"(a[2]), "r"(a[3]), "r"(b0), "r"(b1));
}
__device__ __forceinline__ float ftanh(float u) {
    float a = fabsf(u);
    float t = __expf(-2.f * a);
    float h = __fdividef(1.f - t, 1.f + t);
    return copysignf(h, u);
}
// split store: hi + lo planes at (row, k) (k even, 2 values)
__device__ __forceinline__ void store_split(char* smem, int row, int k,
                                            float vx, float vy) {
    __half hx = __float2half_rn(vx), hy = __float2half_rn(vy);
    float lx = vx - __half2float(hx), ly = vy - __half2float(hy);
    __half2 hp = __halves2half2(hx, hy);
    __half2 lp = __halves2half2(__float2half_rn(lx), __float2half_rn(ly));
    *(u32*)(smem + SM_SHI + row * SROW + k * 2) = *(u32*)&hp;
    *(u32*)(smem + SM_SLO + row * SROW + k * 2) = *(u32*)&lp;
}

// one K=32 chunk of W^T (both planes): 256 rows x 4 x 16B per plane = 1024
// transfers/plane; 1024 threads, one (hi,lo) pair each.
__device__ __forceinline__ void load_chunk(char* smem, int cg, int tid) {
    const int layer = cg >> 3, c = cg & 7, bsel = cg & 1;
    const __half* sh = g_Whi + layer * (HD * HD) + c * 32;
    const __half* sl = g_Wlo + layer * (HD * HD) + c * 32;
    const u32 dH = s2u(smem + SM_WB) + (u32)(bsel * WB_BUF);
    const u32 dL = dH + WB_LO;
    const int n = tid >> 2, s = tid & 3;
    const u32 off = (u32)(n * WROW + s * 16);
    cpasync16(dH + off, sh + n * HD + s * 8);
    cpasync16(dL + off, sl + n * HD + s * 8);
    asm volatile("cp.async.commit_group;");
}

__global__ __launch_bounds__(NTHREADS, 1)
void grad_kernel(const float* __restrict__ x,
                 const float* __restrict__ W0, const float* __restrict__ b0,
                 const float* __restrict__ b1, const float* __restrict__ b2,
                 const float* __restrict__ b3,
                 const float* __restrict__ Wo, const float* __restrict__ bo,
                 float* __restrict__ out) {
    extern __shared__ __align__(16) char smem[];
    const int tid  = threadIdx.x;
    const int wid  = tid >> 5;
    const int lane = tid & 31;
    const int wm = wid & 7, wn = wid >> 3;       // 8 m-tiles x 4 n-blocks
    const int m0 = wm * 16, nb0 = wn * 64;
    const int s0 = blockIdx.x * SAMPLES;

    // ---- stage bias + Wo
    if (tid < HD) {
        ((float*)(smem + SM_BIAS))[tid]        = b1[tid];
        ((float*)(smem + SM_BIAS + 1024))[tid] = b2[tid];
        ((float*)(smem + SM_BIAS + 2048))[tid] = b3[tid];
    }
    if (tid < 512) ((float*)(smem + SM_WO))[tid] = Wo[tid];

    load_chunk(smem, 0, tid);   // prefetch overlaps layer0

    // ---- layer 0: 4 -> 256 jet, write split planes (64 threads per sample)
    {
        const int samp = tid >> 6, kg = tid & 63;
        const float4 xv = __ldg((const float4*)x + (s0 + samp));
#pragma unroll
        for (int jp = 0; jp < 2; jp++) {
            const int k = kg * 4 + jp * 2;
            float vv[2][8];
#pragma unroll
            for (int e = 0; e < 2; e++) {
                const int ke = k + e;
                float w0 = __ldg(W0 + 0 * HD + ke), w1 = __ldg(W0 + 1 * HD + ke);
                float w2 = __ldg(W0 + 2 * HD + ke), w3 = __ldg(W0 + 3 * HD + ke);
                float u0 = __ldg(b0 + ke) + xv.x * w0 + xv.y * w1 + xv.z * w2 + xv.w * w3;
                float h = ftanh(u0), d = 1.f - h * h;
                vv[e][0] = h;
                vv[e][1] = d * w0; vv[e][2] = d * w1; vv[e][3] = d * w2; vv[e][4] = d * w3;
                float c2 = -2.f * h * d;
                vv[e][5] = c2 * w0 * w0; vv[e][6] = c2 * w1 * w1; vv[e][7] = c2 * w2 * w2;
            }
#pragma unroll
            for (int ch = 0; ch < 8; ch++)
                store_split(smem, samp * 8 + ch, k, vv[0][ch], vv[1][ch]);
        }
    }
    __syncthreads();

    // ---- lane bases for ldmatrix
    const int lt = lane >> 3, lr = lane & 7;
    const u32 aBase = (u32)((m0 + ((lt & 1) << 3) + lr) * SROW + ((lt >> 1) << 4));
    const u32 aHi = s2u(smem + SM_SHI) + aBase;
    const u32 aLo = s2u(smem + SM_SLO) + aBase;
    const u32 bOff = (u32)((nb0 + ((lt >> 1) << 3) + lr) * WROW + ((lt & 1) << 4));
    const int q = lane & 3, ch = lane >> 2;
    const int srcl = (ch >= 5) ? (((ch - 4) << 2) + q) : lane;

    float acc[8][4];

    for (int L = 0; L < NLAYER; L++) {
#pragma unroll
        for (int nt = 0; nt < 8; nt++)
#pragma unroll
            for (int j = 0; j < 4; j++) acc[nt][j] = 0.f;

        for (int c = 0; c < 8; c++) {
            const int cg = L * 8 + c;
            if (c > 0) __syncthreads();          // prior chunk's reads done
            if (cg + 1 < TOTCH) {
                load_chunk(smem, cg + 1, tid);
                asm volatile("cp.async.wait_group 1;");
            } else {
                asm volatile("cp.async.wait_group 0;");
            }
            __syncthreads();                     // buffer cg filled & visible

            const u32 wb = s2u(smem + SM_WB) + (u32)((cg & 1) * WB_BUF) + bOff;
#pragma unroll
            for (int kt = 0; kt < 2; kt++) {
                const u32 ka = (u32)(c * 64 + kt * 32);
                u32 Ah[4], Al[4];
                ldsm4(Ah, aHi + ka);
                ldsm4(Al, aLo + ka);
                const u32 wk = wb + (u32)(kt * 32);
#pragma unroll
                for (int np = 0; np < 4; np++) {
                    u32 Bh[4], Bl[4];
                    ldsm4(Bh, wk + (u32)(np * 16 * WROW));
                    ldsm4(Bl, wk + (u32)(np * 16 * WROW) + WB_LO);
                    mma16816(acc[2 * np],     Ah, Bh[0], Bh[1]);
                    mma16816(acc[2 * np],     Ah, Bl[0], Bl[1]);
                    mma16816(acc[2 * np],     Al, Bh[0], Bh[1]);
                    mma16816(acc[2 * np + 1], Ah, Bh[2], Bh[3]);
                    mma16816(acc[2 * np + 1], Ah, Bl[2], Bl[3]);
                    mma16816(acc[2 * np + 1], Al, Bh[2], Bh[3]);
                }
            }
        }
        __syncthreads();   // all A-frag reads of S done before epilogue writes

        // ---- epilogue: tanh-jet in registers, write split planes
        const float* bs = (const float*)(smem + SM_BIAS) + L * HD;
#pragma unroll
        for (int nt = 0; nt < 8; nt++) {
            const int n = nb0 + nt * 8 + 2 * q;
            const float2 bn = *(const float2*)(bs + n);
#pragma unroll
            for (int sh = 0; sh < 2; sh++) {
                float ux = acc[nt][sh * 2 + 0], uy = acc[nt][sh * 2 + 1];
                float u0x = __shfl_sync(0xffffffffu, ux, q);
                float u0y = __shfl_sync(0xffffffffu, uy, q);
                float u1x = __shfl_sync(0xffffffffu, ux, srcl);
                float u1y = __shfl_sync(0xffffffffu, uy, srcl);
                float hx = ftanh(u0x + bn.x), hy = ftanh(u0y + bn.y);
                float dx = 1.f - hx * hx, dy = 1.f - hy * hy;
                float vx, vy;
                if (ch == 0)      { vx = hx; vy = hy; }
                else if (ch < 5)  { vx = dx * ux; vy = dy * uy; }
                else {
                    vx = dx * (ux - 2.f * hx * u1x * u1x);
                    vy = dy * (uy - 2.f * hy * u1y * u1y);
                }
                store_split(smem, m0 + sh * 8 + ch, n, vx, vy);
            }
        }
        __syncthreads();
    }

    // ---- output head: 128 rows x 2 outs; 8 threads per row (32 k each)
    {
        const int m = tid >> 3, kq = tid & 7;
        const char* ph = smem + SM_SHI + m * SROW;
        const char* pl = smem + SM_SLO + m * SROW;
        const float* wos = (const float*)(smem + SM_WO);
        float o0 = 0.f, o1 = 0.f;
#pragma unroll 4
        for (int kk = 0; kk < 16; kk++) {
            const int k = kq * 32 + ((kk + kq * 2) & 15) * 2;   // rotate: no bank clash
            u32 hp = *(const u32*)(ph + k * 2);
            u32 lp = *(const u32*)(pl + k * 2);
            float2 vh = __half22float2(*(__half2*)&hp);
            float2 vl = __half22float2(*(__half2*)&lp);
            float v0 = vh.x + vl.x, v1 = vh.y + vl.y;
            float2 w0 = *(const float2*)(wos + k * 2);
            float2 w1 = *(const float2*)(wos + k * 2 + 2);
            o0 += v0 * w0.x + v1 * w1.x;
            o1 += v0 * w0.y + v1 * w1.y;
        }
        o0 += __shfl_xor_sync(0xffffffffu, o0, 1);
        o0 += __shfl_xor_sync(0xffffffffu, o0, 2);
        o0 += __shfl_xor_sync(0xffffffffu, o0, 4);
        o1 += __shfl_xor_sync(0xffffffffu, o1, 1);
        o1 += __shfl_xor_sync(0xffffffffu, o1, 2);
        o1 += __shfl_xor_sync(0xffffffffu, o1, 4);
        if (kq == 0) {
            if ((m & 7) == 0) { o0 += __ldg(bo); o1 += __ldg(bo + 1); }
            ((float*)(smem + SM_OUT))[m * 2 + 0] = o0;
            ((float*)(smem + SM_OUT))[m * 2 + 1] = o1;
        }
    }
    __syncthreads();

    // ---- per-sample combine + stores
    if (tid < SAMPLES) {
        const float* ob = (const float*)(smem + SM_OUT) + tid * 16;  // [ch][dout]
        float c  = ob[0], Fi = ob[1];
        float cj[4], Fj[4];
#pragma unroll
        for (int i = 0; i < 4; i++) { cj[i] = ob[(1 + i) * 2]; Fj[i] = ob[(1 + i) * 2 + 1]; }
        float trHc = 0.f, FiLap = 0.f;
#pragma unroll
        for (int i = 0; i < 3; i++) { trHc += ob[(5 + i) * 2]; FiLap += ob[(5 + i) * 2 + 1]; }
        float dotg = cj[0] * Fj[0] + cj[1] * Fj[1] + cj[2] * Fj[2];
        float sumg = cj[0] + cj[1] + cj[2];
        float jdiv = -trHc - (dotg + c * FiLap) + 0.1f * sumg;

        const int idx = s0 + tid;
        out[idx]                     = c;
        out[BATCH + idx]             = cj[3];
        out[2 * BATCH + idx * 3 + 0] = cj[0];
        out[2 * BATCH + idx * 3 + 1] = cj[1];
        out[2 * BATCH + idx * 3 + 2] = cj[2];
        out[5 * BATCH + idx]         = Fi;
        out[6 * BATCH + idx * 3 + 0] = Fj[0];
        out[6 * BATCH + idx * 3 + 1] = Fj[1];
        out[6 * BATCH + idx * 3 + 2] = Fj[2];
        out[9 * BATCH + idx]         = FiLap;
        out[10 * BATCH + idx]        = jdiv;
    }
}

extern "C" void kernel_launch(void* const* d_in, const int* in_sizes, int n_in,
                              void* d_out, int out_size) {
    const float* x  = (const float*)d_in[0];
    const float* W0 = (const float*)d_in[1];
    const float* b0 = (const float*)d_in[2];
    const float* W1 = (const float*)d_in[3];
    const float* b1 = (const float*)d_in[4];
    const float* W2 = (const float*)d_in[5];
    const float* b2 = (const float*)d_in[6];
    const float* W3 = (const float*)d_in[7];
    const float* b3 = (const float*)d_in[8];
    const float* Wo = (const float*)d_in[9];
    const float* bo = (const float*)d_in[10];

    prep_split<<<NLAYER * HD, HD>>>(W1, W2, W3);

    cudaFuncSetAttribute(grad_kernel, cudaFuncAttributeMaxDynamicSharedMemorySize, SM_TOT);
    grad_kernel<<<BATCH / SAMPLES, NTHREADS, SM_TOT>>>(x, W0, b0, b1, b2, b3,
                                                       Wo, bo, (float*)d_out);
}